// round 6
// baseline (speedup 1.0000x reference)
#include <cuda_runtime.h>

#define BB   32
#define SS   1024
#define DD   256
#define L1   1030      // conv1 output length
#define L1P  1036      // padded
#define KSEL 515       // k-max k for layer 1
#define CH1  768       // channels after fold1 (128 groups x 6)
#define L2IN 515
#define L2   519       // conv2 output length
#define L2PAD 523
#define CH2  896       // channels after fold2 (64 x 14)
#define CC   1000
#define KF   3584

// scratch (static device globals; no runtime allocation)
__device__ float g_h0[BB * DD * SS];      // (b, d, s) embedded+transposed
__device__ float g_h1[BB * CH1 * KSEL];   // (b, c1, pos) after kmax+tanh
__device__ float g_h3[BB * CH2 * 4];      // (b, c2, 4) after top4+tanh

__device__ __forceinline__ unsigned int f2key(float v) {
    unsigned int u = __float_as_uint(v);
    return u ^ ((u & 0x80000000u) ? 0xFFFFFFFFu : 0x80000000u);
}
__device__ __forceinline__ float key2f(unsigned int k) {
    unsigned int u = k ^ ((k & 0x80000000u) ? 0x80000000u : 0xFFFFFFFFu);
    return __uint_as_float(u);
}

// ---------------------------------------------------------------------------
// Kernel 1: embedding gather + transpose  (B,S) tokens -> g_h0 (b, d, s)
// ---------------------------------------------------------------------------
__global__ __launch_bounds__(256) void k_gather(const int* __restrict__ x,
                                                const float* __restrict__ emb) {
    __shared__ float tile[32][257];
    __shared__ int toks[32];
    int b = blockIdx.y;
    int sBase = blockIdx.x * 32;
    int t = threadIdx.x;
    if (t < 32) toks[t] = x[b * SS + sBase + t];
    __syncthreads();
#pragma unroll 4
    for (int i = 0; i < 32; i++)
        tile[i][t] = emb[(unsigned)toks[i] * DD + t];   // coalesced 1KB row read
    __syncthreads();
    int sl = t & 31, wg = t >> 5;
#pragma unroll 4
    for (int r = 0; r < 32; r++) {
        int d = wg * 32 + r;
        g_h0[((b * DD + d) << 10) + sBase + sl] = tile[sl][d];  // coalesced write
    }
}

// block-wide exclusive scan of packed u64 counters (256 threads)
__device__ __forceinline__ unsigned long long scanExcl64(unsigned long long v,
                                                         unsigned long long* tmp) {
    int lane = threadIdx.x & 31, wid = threadIdx.x >> 5;
    unsigned long long inc = v;
#pragma unroll
    for (int o = 1; o < 32; o <<= 1) {
        unsigned long long n = __shfl_up_sync(0xffffffffu, inc, o);
        if (lane >= o) inc += n;
    }
    if (lane == 31) tmp[wid] = inc;
    __syncthreads();
    unsigned long long off = 0;
#pragma unroll
    for (int w = 0; w < 8; w++)
        if (w < wid) off += tmp[w];
    __syncthreads();          // protect tmp for the next scan
    return off + inc - v;
}

// ---------------------------------------------------------------------------
// Kernel 2: conv1(K=7, depthwise) + fold(pair-sum) + order-preserving
//           k-max(515 of 1030) + tanh.   One block per (b, fold-row r).
// ---------------------------------------------------------------------------
__global__ __launch_bounds__(256) void k_conv1(const float* __restrict__ w1,
                                               const float* __restrict__ b1) {
    __shared__ float e0[L1P], e1[L1P];
    __shared__ float wsh[84];     // 12 filter rows x 7 taps
    __shared__ float bsh[6];
    __shared__ unsigned long long redA[8], redB[8];
    __shared__ unsigned long long totA, totB;
    __shared__ int eqRun[6], keptRun[6];

    int r = blockIdx.x, b = blockIdx.y;
    int t = threadIdx.x;
    int lane = t & 31, wid = t >> 5;

    const float* src0 = g_h0 + ((b * DD + 2 * r) << 10);
    for (int m = t; m < L1P; m += 256) {
        float v0 = 0.f, v1 = 0.f;
        if (m >= 6 && m < 6 + SS) { v0 = src0[m - 6]; v1 = src0[SS + m - 6]; }
        e0[m] = v0; e1[m] = v1;
    }
    if (t < 84) {
        int fr = t / 7, k = t - fr * 7;
        int o = (fr < 6) ? ((2 * r) * 6 + fr) : ((2 * r + 1) * 6 + (fr - 6));
        wsh[t] = w1[o * 7 + k];
    }
    if (t < 6) {
        bsh[t] = b1[(2 * r) * 6 + t] + b1[(2 * r + 1) * 6 + t];
        eqRun[t] = 0; keptRun[t] = 0;
    }
    __syncthreads();

    // compute conv+fold for 6 rows, keep monotonic keys in registers
    unsigned int key[6][5];
#pragma unroll
    for (int f = 0; f < 6; f++) {
#pragma unroll
        for (int i = 0; i < 5; i++) {
            int l = i * 256 + t;
            unsigned int kk = 0u;
            if (l < L1) {
                float acc = bsh[f];
#pragma unroll
                for (int k = 0; k < 7; k++)
                    acc = fmaf(e0[l + k], wsh[f * 7 + k],
                          fmaf(e1[l + k], wsh[(f + 6) * 7 + k], acc));
                kk = f2key(acc);
            }
            key[f][i] = kk;
        }
    }

    // bitwise binary search for the 515th-largest key of each of the 6 rows
    unsigned int T[6] = {0, 0, 0, 0, 0, 0};
    for (int bit = 31; bit >= 0; bit--) {
        unsigned int bm = 1u << bit;
        unsigned int c0 = 0, c1 = 0, c2 = 0, c3 = 0, c4 = 0, c5 = 0;
#pragma unroll
        for (int i = 0; i < 5; i++) {
            c0 += (key[0][i] >= (T[0] | bm));
            c1 += (key[1][i] >= (T[1] | bm));
            c2 += (key[2][i] >= (T[2] | bm));
            c3 += (key[3][i] >= (T[3] | bm));
            c4 += (key[4][i] >= (T[4] | bm));
            c5 += (key[5][i] >= (T[5] | bm));
        }
        unsigned long long pa = (unsigned long long)c0 |
                                ((unsigned long long)c1 << 21) |
                                ((unsigned long long)c2 << 42);
        unsigned long long pb = (unsigned long long)c3 |
                                ((unsigned long long)c4 << 21) |
                                ((unsigned long long)c5 << 42);
#pragma unroll
        for (int o = 16; o; o >>= 1) {
            pa += __shfl_down_sync(0xffffffffu, pa, o);
            pb += __shfl_down_sync(0xffffffffu, pb, o);
        }
        if (lane == 0) { redA[wid] = pa; redB[wid] = pb; }
        __syncthreads();
        if (t == 0) {
            unsigned long long sa = 0, sb = 0;
#pragma unroll
            for (int w = 0; w < 8; w++) { sa += redA[w]; sb += redB[w]; }
            totA = sa; totB = sb;
        }
        __syncthreads();
        unsigned long long sa = totA, sb = totB;
        if (((sa)       & 0x1FFFFFu) >= KSEL) T[0] |= bm;
        if (((sa >> 21) & 0x1FFFFFu) >= KSEL) T[1] |= bm;
        if (((sa >> 42) & 0x1FFFFFu) >= KSEL) T[2] |= bm;
        if (((sb)       & 0x1FFFFFu) >= KSEL) T[3] |= bm;
        if (((sb >> 21) & 0x1FFFFFu) >= KSEL) T[4] |= bm;
        if (((sb >> 42) & 0x1FFFFFu) >= KSEL) T[5] |= bm;
    }

    // g = count(key > T); limit = KSEL - g equal-to-threshold elements kept
    int limit[6];
    {
        unsigned int c0 = 0, c1 = 0, c2 = 0, c3 = 0, c4 = 0, c5 = 0;
#pragma unroll
        for (int i = 0; i < 5; i++) {
            c0 += (key[0][i] > T[0]);
            c1 += (key[1][i] > T[1]);
            c2 += (key[2][i] > T[2]);
            c3 += (key[3][i] > T[3]);
            c4 += (key[4][i] > T[4]);
            c5 += (key[5][i] > T[5]);
        }
        unsigned long long pa = (unsigned long long)c0 |
                                ((unsigned long long)c1 << 21) |
                                ((unsigned long long)c2 << 42);
        unsigned long long pb = (unsigned long long)c3 |
                                ((unsigned long long)c4 << 21) |
                                ((unsigned long long)c5 << 42);
#pragma unroll
        for (int o = 16; o; o >>= 1) {
            pa += __shfl_down_sync(0xffffffffu, pa, o);
            pb += __shfl_down_sync(0xffffffffu, pb, o);
        }
        if (lane == 0) { redA[wid] = pa; redB[wid] = pb; }
        __syncthreads();
        if (t == 0) {
            unsigned long long sa = 0, sb = 0;
#pragma unroll
            for (int w = 0; w < 8; w++) { sa += redA[w]; sb += redB[w]; }
            totA = sa; totB = sb;
        }
        __syncthreads();
        unsigned long long sa = totA, sb = totB;
        limit[0] = KSEL - (int)((sa)       & 0x1FFFFFu);
        limit[1] = KSEL - (int)((sa >> 21) & 0x1FFFFFu);
        limit[2] = KSEL - (int)((sa >> 42) & 0x1FFFFFu);
        limit[3] = KSEL - (int)((sb)       & 0x1FFFFFu);
        limit[4] = KSEL - (int)((sb >> 21) & 0x1FFFFFu);
        limit[5] = KSEL - (int)((sb >> 42) & 0x1FFFFFu);
    }

    // stable (order-preserving) compaction with tanh on write
    float* outBase = g_h1 + (unsigned)(b * CH1 + r * 6) * KSEL;
#pragma unroll
    for (int i = 0; i < 5; i++) {
        int l = i * 256 + t;
        int valid = (l < L1);
        unsigned int isG[6], isE[6];
        unsigned long long ep = 0;
#pragma unroll
        for (int f = 0; f < 6; f++) {
            unsigned int kk = key[f][i];
            isG[f] = valid && (kk > T[f]);
            isE[f] = valid && (kk == T[f]);
            ep |= (unsigned long long)isE[f] << (9 * f);
        }
        unsigned long long eEx = scanExcl64(ep, redA);
        unsigned long long kp = 0;
        unsigned int kept[6];
#pragma unroll
        for (int f = 0; f < 6; f++) {
            int eqB = eqRun[f] + (int)((eEx >> (9 * f)) & 511u);
            kept[f] = isG[f] | (isE[f] & (unsigned)(eqB < limit[f]));
            kp |= (unsigned long long)kept[f] << (9 * f);
        }
        unsigned long long kEx = scanExcl64(kp, redA);
#pragma unroll
        for (int f = 0; f < 6; f++) {
            if (kept[f]) {
                int pos = keptRun[f] + (int)((kEx >> (9 * f)) & 511u);
                outBase[f * KSEL + pos] = tanhf(key2f(key[f][i]));
            }
        }
        __syncthreads();
        if (t == 255) {
            unsigned long long eInc = eEx + ep, kInc = kEx + kp;
#pragma unroll
            for (int f = 0; f < 6; f++) {
                eqRun[f]   += (int)((eInc >> (9 * f)) & 511u);
                keptRun[f] += (int)((kInc >> (9 * f)) & 511u);
            }
        }
        __syncthreads();
    }
}

// top-4 merge of two descending sorted-4 u64 lists (bitonic halver + cleanup)
#define MERGE4(a0, a1, a2, a3, q0, q1, q2, q3)                                  \
    {                                                                           \
        unsigned long long m0 = (a0) > (q3) ? (a0) : (q3);                      \
        unsigned long long m1 = (a1) > (q2) ? (a1) : (q2);                      \
        unsigned long long m2 = (a2) > (q1) ? (a2) : (q1);                      \
        unsigned long long m3 = (a3) > (q0) ? (a3) : (q0);                      \
        unsigned long long d0 = m0 > m2 ? m0 : m2, d2 = m0 > m2 ? m2 : m0;      \
        unsigned long long d1 = m1 > m3 ? m1 : m3, d3 = m1 > m3 ? m3 : m1;      \
        a0 = d0 > d1 ? d0 : d1; a1 = d0 > d1 ? d1 : d0;                         \
        a2 = d2 > d3 ? d2 : d3; a3 = d2 > d3 ? d3 : d2;                         \
    }

// ---------------------------------------------------------------------------
// Kernel 3: conv2(K=5, grouped 6->14) + fold + order-preserving top-4 + tanh
//           One block per (b, fold-row r2). Never materializes conv2 output.
// ---------------------------------------------------------------------------
__global__ __launch_bounds__(256) void k_conv2(const float* __restrict__ w2,
                                               const float* __restrict__ b2) {
    __shared__ float in[12][L2PAD];
    __shared__ float wsh[840];   // 28 filter rows x 30 (6 ich x 5 taps)
    __shared__ float bsh[14];
    __shared__ unsigned long long lists[8][4];

    int r2 = blockIdx.x, b = blockIdx.y;
    int t = threadIdx.x, lane = t & 31, wid = t >> 5;

    const float* src = g_h1 + (unsigned)(b * CH1 + r2 * 12) * KSEL;
    for (int idx = t; idx < 12 * L2PAD; idx += 256) {
        int row = idx / L2PAD, m = idx - row * L2PAD;
        float v = 0.f;
        if (m >= 4 && m < 4 + L2IN) v = src[row * KSEL + (m - 4)];
        in[row][m] = v;
    }
    for (int idx = t; idx < 840; idx += 256) {
        int fr = idx / 30, rem = idx - fr * 30;
        int g = 2 * r2 + (fr >= 14);
        int f = (fr >= 14) ? fr - 14 : fr;
        wsh[idx] = w2[(g * 14 + f) * 30 + rem];
    }
    if (t < 14) bsh[t] = b2[(2 * r2) * 14 + t] + b2[(2 * r2 + 1) * 14 + t];
    __syncthreads();

    for (int f = 0; f < 14; f++) {
        unsigned long long s0 = 0, s1 = 0, s2 = 0, s3 = 0;
        const float* wa = wsh + f * 30;
        const float* wb = wsh + (14 + f) * 30;
#pragma unroll
        for (int i = 0; i < 3; i++) {
            int l = i * 256 + t;
            if (l < L2) {
                float acc = bsh[f];
#pragma unroll
                for (int ci = 0; ci < 6; ci++) {
#pragma unroll
                    for (int k = 0; k < 5; k++) {
                        acc = fmaf(in[ci][l + k],     wa[ci * 5 + k], acc);
                        acc = fmaf(in[6 + ci][l + k], wb[ci * 5 + k], acc);
                    }
                }
                unsigned long long e = ((unsigned long long)f2key(acc) << 32) |
                                       (unsigned int)(1023 - l);  // lower idx wins ties
                if      (e > s0) { s3 = s2; s2 = s1; s1 = s0; s0 = e; }
                else if (e > s1) { s3 = s2; s2 = s1; s1 = e; }
                else if (e > s2) { s3 = s2; s2 = e; }
                else if (e > s3) { s3 = e; }
            }
        }
        // warp-level merge of sorted-4 lists
#pragma unroll
        for (int off = 16; off; off >>= 1) {
            unsigned long long q0 = __shfl_down_sync(0xffffffffu, s0, off);
            unsigned long long q1 = __shfl_down_sync(0xffffffffu, s1, off);
            unsigned long long q2 = __shfl_down_sync(0xffffffffu, s2, off);
            unsigned long long q3 = __shfl_down_sync(0xffffffffu, s3, off);
            MERGE4(s0, s1, s2, s3, q0, q1, q2, q3)
        }
        if (lane == 0) {
            lists[wid][0] = s0; lists[wid][1] = s1;
            lists[wid][2] = s2; lists[wid][3] = s3;
        }
        __syncthreads();
        if (t == 0) {
            unsigned long long a0 = lists[0][0], a1 = lists[0][1];
            unsigned long long a2 = lists[0][2], a3 = lists[0][3];
            for (int w = 1; w < 8; w++) {
                unsigned long long q0 = lists[w][0], q1 = lists[w][1];
                unsigned long long q2 = lists[w][2], q3 = lists[w][3];
                MERGE4(a0, a1, a2, a3, q0, q1, q2, q3)
            }
            unsigned long long ss[4] = {a0, a1, a2, a3};
            int   idx4[4]; float val4[4];
#pragma unroll
            for (int j = 0; j < 4; j++) {
                idx4[j] = 1023 - (int)(unsigned int)(ss[j] & 0xffffffffu);
                val4[j] = key2f((unsigned int)(ss[j] >> 32));
            }
            // restore original index order
#define CSW(a, bq)                                                              \
    if (idx4[a] > idx4[bq]) {                                                   \
        int ti = idx4[a]; idx4[a] = idx4[bq]; idx4[bq] = ti;                    \
        float tv = val4[a]; val4[a] = val4[bq]; val4[bq] = tv;                   \
    }
            CSW(0, 1) CSW(2, 3) CSW(0, 2) CSW(1, 3) CSW(1, 2)
#undef CSW
            float* o = g_h3 + (unsigned)(b * CH2 + (r2 * 14 + f)) * 4;
            o[0] = tanhf(val4[0]); o[1] = tanhf(val4[1]);
            o[2] = tanhf(val4[2]); o[3] = tanhf(val4[3]);
        }
        __syncthreads();
    }
}

// ---------------------------------------------------------------------------
// Kernel 4: out(32,1000) = h3(32,3584) @ wf(1000,3584)^T + bf
// ---------------------------------------------------------------------------
__global__ __launch_bounds__(256) void k_fc(const float* __restrict__ wf,
                                            const float* __restrict__ bf,
                                            float* __restrict__ out) {
    __shared__ float sh[32][65];
    __shared__ float sw[16][64];
    int t = threadIdx.x;
    int cBase = blockIdx.x * 16;
    int lane = t & 31;       // b
    int w = t >> 5;          // 0..7 -> c rows w and w+8
    float acc0 = 0.f, acc1 = 0.f;
    const float* hsrc = g_h3;   // flat (b, 3584)
    for (int kt = 0; kt < 56; kt++) {
        int k0 = kt * 64;
#pragma unroll
        for (int i = 0; i < 8; i++) {
            int idx = t + i * 256;
            int bb = idx >> 6, jj = idx & 63;
            sh[bb][jj] = hsrc[bb * KF + k0 + jj];
        }
#pragma unroll
        for (int i = 0; i < 4; i++) {
            int idx = t + i * 256;
            int rr = idx >> 6, jj = idx & 63;
            int c = cBase + rr;
            sw[rr][jj] = (c < CC) ? wf[c * KF + k0 + jj] : 0.f;
        }
        __syncthreads();
#pragma unroll
        for (int jj = 0; jj < 64; jj++) {
            float hv = sh[lane][jj];
            acc0 = fmaf(hv, sw[w][jj], acc0);
            acc1 = fmaf(hv, sw[w + 8][jj], acc1);
        }
        __syncthreads();
    }
    int c0 = cBase + w, c1 = cBase + w + 8;
    if (c0 < CC) out[lane * CC + c0] = acc0 + bf[c0];
    if (c1 < CC) out[lane * CC + c1] = acc1 + bf[c1];
}

extern "C" void kernel_launch(void* const* d_in, const int* in_sizes, int n_in,
                              void* d_out, int out_size) {
    (void)in_sizes; (void)n_in; (void)out_size;
    const int*   x   = (const int*)d_in[0];
    const float* emb = (const float*)d_in[1];
    const float* w1  = (const float*)d_in[2];
    const float* b1  = (const float*)d_in[3];
    const float* w2  = (const float*)d_in[4];
    const float* b2  = (const float*)d_in[5];
    const float* wf  = (const float*)d_in[6];
    const float* bf  = (const float*)d_in[7];
    float* out = (float*)d_out;

    k_gather<<<dim3(32, 32), 256>>>(x, emb);
    k_conv1<<<dim3(128, 32), 256>>>(w1, b1);
    k_conv2<<<dim3(64, 32), 256>>>(w2, b2);
    k_fc<<<63, 256>>>(wf, bf, out);
}

// round 7
// speedup vs baseline: 1.0004x; 1.0004x over previous
#include <cuda_runtime.h>

#define BB   32
#define SS   1024
#define DD   256
#define L1   1030      // conv1 output length
#define L1P  1036      // padded
#define KSEL 515       // k-max k for layer 1
#define CH1  768       // channels after fold1 (128 groups x 6)
#define L2IN 515
#define L2   519       // conv2 output length
#define L2PAD 523
#define CH2  896       // channels after fold2 (64 x 14)
#define CC   1000
#define KF   3584

// scratch (static device globals; no runtime allocation)
__device__ float g_h0[BB * DD * SS];      // (b, d, s) embedded+transposed
__device__ float g_h1[BB * CH1 * KSEL];   // (b, c1, pos) after kmax+tanh
__device__ float g_h3[BB * CH2 * 4];      // (b, c2, 4) after top4+tanh

__device__ __forceinline__ unsigned int f2key(float v) {
    unsigned int u = __float_as_uint(v);
    return u ^ ((u & 0x80000000u) ? 0xFFFFFFFFu : 0x80000000u);
}
__device__ __forceinline__ float key2f(unsigned int k) {
    unsigned int u = k ^ ((k & 0x80000000u) ? 0x80000000u : 0xFFFFFFFFu);
    return __uint_as_float(u);
}

// ---------------------------------------------------------------------------
// Kernel 1: embedding gather + transpose  (B,S) tokens -> g_h0 (b, d, s)
// ---------------------------------------------------------------------------
__global__ __launch_bounds__(256) void k_gather(const int* __restrict__ x,
                                                const float* __restrict__ emb) {
    __shared__ float tile[32][257];
    __shared__ int toks[32];
    int b = blockIdx.y;
    int sBase = blockIdx.x * 32;
    int t = threadIdx.x;
    if (t < 32) toks[t] = x[b * SS + sBase + t];
    __syncthreads();
#pragma unroll 4
    for (int i = 0; i < 32; i++)
        tile[i][t] = emb[(unsigned)toks[i] * DD + t];   // coalesced 1KB row read
    __syncthreads();
    int sl = t & 31, wg = t >> 5;
#pragma unroll 4
    for (int r = 0; r < 32; r++) {
        int d = wg * 32 + r;
        g_h0[((b * DD + d) << 10) + sBase + sl] = tile[sl][d];  // coalesced write
    }
}

// block-wide exclusive scan of packed u64 counters (256 threads)
__device__ __forceinline__ unsigned long long scanExcl64(unsigned long long v,
                                                         unsigned long long* tmp) {
    int lane = threadIdx.x & 31, wid = threadIdx.x >> 5;
    unsigned long long inc = v;
#pragma unroll
    for (int o = 1; o < 32; o <<= 1) {
        unsigned long long n = __shfl_up_sync(0xffffffffu, inc, o);
        if (lane >= o) inc += n;
    }
    if (lane == 31) tmp[wid] = inc;
    __syncthreads();
    unsigned long long off = 0;
#pragma unroll
    for (int w = 0; w < 8; w++)
        if (w < wid) off += tmp[w];
    __syncthreads();          // protect tmp for the next scan
    return off + inc - v;
}

// ---------------------------------------------------------------------------
// Kernel 2: conv1(K=7, depthwise) + fold(pair-sum) + order-preserving
//           k-max(515 of 1030) + tanh.   One block per (b, fold-row r).
// ---------------------------------------------------------------------------
__global__ __launch_bounds__(256) void k_conv1(const float* __restrict__ w1,
                                               const float* __restrict__ b1) {
    __shared__ float e0[L1P], e1[L1P];
    __shared__ float wsh[84];     // 12 filter rows x 7 taps
    __shared__ float bsh[6];
    __shared__ unsigned long long redA[8], redB[8];
    __shared__ unsigned long long totA, totB;
    __shared__ int eqRun[6], keptRun[6];

    int r = blockIdx.x, b = blockIdx.y;
    int t = threadIdx.x;
    int lane = t & 31, wid = t >> 5;

    const float* src0 = g_h0 + ((b * DD + 2 * r) << 10);
    for (int m = t; m < L1P; m += 256) {
        float v0 = 0.f, v1 = 0.f;
        if (m >= 6 && m < 6 + SS) { v0 = src0[m - 6]; v1 = src0[SS + m - 6]; }
        e0[m] = v0; e1[m] = v1;
    }
    if (t < 84) {
        int fr = t / 7, k = t - fr * 7;
        int o = (fr < 6) ? ((2 * r) * 6 + fr) : ((2 * r + 1) * 6 + (fr - 6));
        wsh[t] = w1[o * 7 + k];
    }
    if (t < 6) {
        bsh[t] = b1[(2 * r) * 6 + t] + b1[(2 * r + 1) * 6 + t];
        eqRun[t] = 0; keptRun[t] = 0;
    }
    __syncthreads();

    // compute conv+fold for 6 rows, keep monotonic keys in registers
    unsigned int key[6][5];
#pragma unroll
    for (int f = 0; f < 6; f++) {
#pragma unroll
        for (int i = 0; i < 5; i++) {
            int l = i * 256 + t;
            unsigned int kk = 0u;
            if (l < L1) {
                float acc = bsh[f];
#pragma unroll
                for (int k = 0; k < 7; k++)
                    acc = fmaf(e0[l + k], wsh[f * 7 + k],
                          fmaf(e1[l + k], wsh[(f + 6) * 7 + k], acc));
                kk = f2key(acc);
            }
            key[f][i] = kk;
        }
    }

    // bitwise binary search for the 515th-largest key of each of the 6 rows
    unsigned int T[6] = {0, 0, 0, 0, 0, 0};
    for (int bit = 31; bit >= 0; bit--) {
        unsigned int bm = 1u << bit;
        unsigned int c0 = 0, c1 = 0, c2 = 0, c3 = 0, c4 = 0, c5 = 0;
#pragma unroll
        for (int i = 0; i < 5; i++) {
            c0 += (key[0][i] >= (T[0] | bm));
            c1 += (key[1][i] >= (T[1] | bm));
            c2 += (key[2][i] >= (T[2] | bm));
            c3 += (key[3][i] >= (T[3] | bm));
            c4 += (key[4][i] >= (T[4] | bm));
            c5 += (key[5][i] >= (T[5] | bm));
        }
        unsigned long long pa = (unsigned long long)c0 |
                                ((unsigned long long)c1 << 21) |
                                ((unsigned long long)c2 << 42);
        unsigned long long pb = (unsigned long long)c3 |
                                ((unsigned long long)c4 << 21) |
                                ((unsigned long long)c5 << 42);
#pragma unroll
        for (int o = 16; o; o >>= 1) {
            pa += __shfl_down_sync(0xffffffffu, pa, o);
            pb += __shfl_down_sync(0xffffffffu, pb, o);
        }
        if (lane == 0) { redA[wid] = pa; redB[wid] = pb; }
        __syncthreads();
        if (t == 0) {
            unsigned long long sa = 0, sb = 0;
#pragma unroll
            for (int w = 0; w < 8; w++) { sa += redA[w]; sb += redB[w]; }
            totA = sa; totB = sb;
        }
        __syncthreads();
        unsigned long long sa = totA, sb = totB;
        if (((sa)       & 0x1FFFFFu) >= KSEL) T[0] |= bm;
        if (((sa >> 21) & 0x1FFFFFu) >= KSEL) T[1] |= bm;
        if (((sa >> 42) & 0x1FFFFFu) >= KSEL) T[2] |= bm;
        if (((sb)       & 0x1FFFFFu) >= KSEL) T[3] |= bm;
        if (((sb >> 21) & 0x1FFFFFu) >= KSEL) T[4] |= bm;
        if (((sb >> 42) & 0x1FFFFFu) >= KSEL) T[5] |= bm;
    }

    // g = count(key > T); limit = KSEL - g equal-to-threshold elements kept
    int limit[6];
    {
        unsigned int c0 = 0, c1 = 0, c2 = 0, c3 = 0, c4 = 0, c5 = 0;
#pragma unroll
        for (int i = 0; i < 5; i++) {
            c0 += (key[0][i] > T[0]);
            c1 += (key[1][i] > T[1]);
            c2 += (key[2][i] > T[2]);
            c3 += (key[3][i] > T[3]);
            c4 += (key[4][i] > T[4]);
            c5 += (key[5][i] > T[5]);
        }
        unsigned long long pa = (unsigned long long)c0 |
                                ((unsigned long long)c1 << 21) |
                                ((unsigned long long)c2 << 42);
        unsigned long long pb = (unsigned long long)c3 |
                                ((unsigned long long)c4 << 21) |
                                ((unsigned long long)c5 << 42);
#pragma unroll
        for (int o = 16; o; o >>= 1) {
            pa += __shfl_down_sync(0xffffffffu, pa, o);
            pb += __shfl_down_sync(0xffffffffu, pb, o);
        }
        if (lane == 0) { redA[wid] = pa; redB[wid] = pb; }
        __syncthreads();
        if (t == 0) {
            unsigned long long sa = 0, sb = 0;
#pragma unroll
            for (int w = 0; w < 8; w++) { sa += redA[w]; sb += redB[w]; }
            totA = sa; totB = sb;
        }
        __syncthreads();
        unsigned long long sa = totA, sb = totB;
        limit[0] = KSEL - (int)((sa)       & 0x1FFFFFu);
        limit[1] = KSEL - (int)((sa >> 21) & 0x1FFFFFu);
        limit[2] = KSEL - (int)((sa >> 42) & 0x1FFFFFu);
        limit[3] = KSEL - (int)((sb)       & 0x1FFFFFu);
        limit[4] = KSEL - (int)((sb >> 21) & 0x1FFFFFu);
        limit[5] = KSEL - (int)((sb >> 42) & 0x1FFFFFu);
    }

    // stable (order-preserving) compaction with tanh on write
    float* outBase = g_h1 + (unsigned)(b * CH1 + r * 6) * KSEL;
#pragma unroll
    for (int i = 0; i < 5; i++) {
        int l = i * 256 + t;
        int valid = (l < L1);
        unsigned int isG[6], isE[6];
        unsigned long long ep = 0;
#pragma unroll
        for (int f = 0; f < 6; f++) {
            unsigned int kk = key[f][i];
            isG[f] = valid && (kk > T[f]);
            isE[f] = valid && (kk == T[f]);
            ep |= (unsigned long long)isE[f] << (9 * f);
        }
        unsigned long long eEx = scanExcl64(ep, redA);
        unsigned long long kp = 0;
        unsigned int kept[6];
#pragma unroll
        for (int f = 0; f < 6; f++) {
            int eqB = eqRun[f] + (int)((eEx >> (9 * f)) & 511u);
            kept[f] = isG[f] | (isE[f] & (unsigned)(eqB < limit[f]));
            kp |= (unsigned long long)kept[f] << (9 * f);
        }
        unsigned long long kEx = scanExcl64(kp, redA);
#pragma unroll
        for (int f = 0; f < 6; f++) {
            if (kept[f]) {
                int pos = keptRun[f] + (int)((kEx >> (9 * f)) & 511u);
                outBase[f * KSEL + pos] = tanhf(key2f(key[f][i]));
            }
        }
        __syncthreads();
        if (t == 255) {
            unsigned long long eInc = eEx + ep, kInc = kEx + kp;
#pragma unroll
            for (int f = 0; f < 6; f++) {
                eqRun[f]   += (int)((eInc >> (9 * f)) & 511u);
                keptRun[f] += (int)((kInc >> (9 * f)) & 511u);
            }
        }
        __syncthreads();
    }
}

// top-4 merge of two descending sorted-4 u64 lists (bitonic halver + cleanup)
#define MERGE4(a0, a1, a2, a3, q0, q1, q2, q3)                                  \
    {                                                                           \
        unsigned long long m0 = (a0) > (q3) ? (a0) : (q3);                      \
        unsigned long long m1 = (a1) > (q2) ? (a1) : (q2);                      \
        unsigned long long m2 = (a2) > (q1) ? (a2) : (q1);                      \
        unsigned long long m3 = (a3) > (q0) ? (a3) : (q0);                      \
        unsigned long long d0 = m0 > m2 ? m0 : m2, d2 = m0 > m2 ? m2 : m0;      \
        unsigned long long d1 = m1 > m3 ? m1 : m3, d3 = m1 > m3 ? m3 : m1;      \
        a0 = d0 > d1 ? d0 : d1; a1 = d0 > d1 ? d1 : d0;                         \
        a2 = d2 > d3 ? d2 : d3; a3 = d2 > d3 ? d3 : d2;                         \
    }

// ---------------------------------------------------------------------------
// Kernel 3: conv2(K=5, grouped 6->14) + fold + order-preserving top-4 + tanh
//           One block per (b, fold-row r2). Never materializes conv2 output.
// ---------------------------------------------------------------------------
__global__ __launch_bounds__(256) void k_conv2(const float* __restrict__ w2,
                                               const float* __restrict__ b2) {
    __shared__ float in[12][L2PAD];
    __shared__ float wsh[840];   // 28 filter rows x 30 (6 ich x 5 taps)
    __shared__ float bsh[14];
    __shared__ unsigned long long lists[8][4];

    int r2 = blockIdx.x, b = blockIdx.y;
    int t = threadIdx.x, lane = t & 31, wid = t >> 5;

    const float* src = g_h1 + (unsigned)(b * CH1 + r2 * 12) * KSEL;
    for (int idx = t; idx < 12 * L2PAD; idx += 256) {
        int row = idx / L2PAD, m = idx - row * L2PAD;
        float v = 0.f;
        if (m >= 4 && m < 4 + L2IN) v = src[row * KSEL + (m - 4)];
        in[row][m] = v;
    }
    for (int idx = t; idx < 840; idx += 256) {
        int fr = idx / 30, rem = idx - fr * 30;
        int g = 2 * r2 + (fr >= 14);
        int f = (fr >= 14) ? fr - 14 : fr;
        wsh[idx] = w2[(g * 14 + f) * 30 + rem];
    }
    if (t < 14) bsh[t] = b2[(2 * r2) * 14 + t] + b2[(2 * r2 + 1) * 14 + t];
    __syncthreads();

    for (int f = 0; f < 14; f++) {
        unsigned long long s0 = 0, s1 = 0, s2 = 0, s3 = 0;
        const float* wa = wsh + f * 30;
        const float* wb = wsh + (14 + f) * 30;
#pragma unroll
        for (int i = 0; i < 3; i++) {
            int l = i * 256 + t;
            if (l < L2) {
                float acc = bsh[f];
#pragma unroll
                for (int ci = 0; ci < 6; ci++) {
#pragma unroll
                    for (int k = 0; k < 5; k++) {
                        acc = fmaf(in[ci][l + k],     wa[ci * 5 + k], acc);
                        acc = fmaf(in[6 + ci][l + k], wb[ci * 5 + k], acc);
                    }
                }
                unsigned long long e = ((unsigned long long)f2key(acc) << 32) |
                                       (unsigned int)(1023 - l);  // lower idx wins ties
                if      (e > s0) { s3 = s2; s2 = s1; s1 = s0; s0 = e; }
                else if (e > s1) { s3 = s2; s2 = s1; s1 = e; }
                else if (e > s2) { s3 = s2; s2 = e; }
                else if (e > s3) { s3 = e; }
            }
        }
        // warp-level merge of sorted-4 lists
#pragma unroll
        for (int off = 16; off; off >>= 1) {
            unsigned long long q0 = __shfl_down_sync(0xffffffffu, s0, off);
            unsigned long long q1 = __shfl_down_sync(0xffffffffu, s1, off);
            unsigned long long q2 = __shfl_down_sync(0xffffffffu, s2, off);
            unsigned long long q3 = __shfl_down_sync(0xffffffffu, s3, off);
            MERGE4(s0, s1, s2, s3, q0, q1, q2, q3)
        }
        if (lane == 0) {
            lists[wid][0] = s0; lists[wid][1] = s1;
            lists[wid][2] = s2; lists[wid][3] = s3;
        }
        __syncthreads();
        if (t == 0) {
            unsigned long long a0 = lists[0][0], a1 = lists[0][1];
            unsigned long long a2 = lists[0][2], a3 = lists[0][3];
            for (int w = 1; w < 8; w++) {
                unsigned long long q0 = lists[w][0], q1 = lists[w][1];
                unsigned long long q2 = lists[w][2], q3 = lists[w][3];
                MERGE4(a0, a1, a2, a3, q0, q1, q2, q3)
            }
            unsigned long long ss[4] = {a0, a1, a2, a3};
            int   idx4[4]; float val4[4];
#pragma unroll
            for (int j = 0; j < 4; j++) {
                idx4[j] = 1023 - (int)(unsigned int)(ss[j] & 0xffffffffu);
                val4[j] = key2f((unsigned int)(ss[j] >> 32));
            }
            // restore original index order
#define CSW(a, bq)                                                              \
    if (idx4[a] > idx4[bq]) {                                                   \
        int ti = idx4[a]; idx4[a] = idx4[bq]; idx4[bq] = ti;                    \
        float tv = val4[a]; val4[a] = val4[bq]; val4[bq] = tv;                   \
    }
            CSW(0, 1) CSW(2, 3) CSW(0, 2) CSW(1, 3) CSW(1, 2)
#undef CSW
            float* o = g_h3 + (unsigned)(b * CH2 + (r2 * 14 + f)) * 4;
            o[0] = tanhf(val4[0]); o[1] = tanhf(val4[1]);
            o[2] = tanhf(val4[2]); o[3] = tanhf(val4[3]);
        }
        __syncthreads();
    }
}

// ---------------------------------------------------------------------------
// Kernel 4: out(32,1000) = h3(32,3584) @ wf(1000,3584)^T + bf
// ---------------------------------------------------------------------------
__global__ __launch_bounds__(256) void k_fc(const float* __restrict__ wf,
                                            const float* __restrict__ bf,
                                            float* __restrict__ out) {
    __shared__ float sh[32][65];
    __shared__ float sw[16][64];
    int t = threadIdx.x;
    int cBase = blockIdx.x * 16;
    int lane = t & 31;       // b
    int w = t >> 5;          // 0..7 -> c rows w and w+8
    float acc0 = 0.f, acc1 = 0.f;
    const float* hsrc = g_h3;   // flat (b, 3584)
    for (int kt = 0; kt < 56; kt++) {
        int k0 = kt * 64;
#pragma unroll
        for (int i = 0; i < 8; i++) {
            int idx = t + i * 256;
            int bb = idx >> 6, jj = idx & 63;
            sh[bb][jj] = hsrc[bb * KF + k0 + jj];
        }
#pragma unroll
        for (int i = 0; i < 4; i++) {
            int idx = t + i * 256;
            int rr = idx >> 6, jj = idx & 63;
            int c = cBase + rr;
            sw[rr][jj] = (c < CC) ? wf[c * KF + k0 + jj] : 0.f;
        }
        __syncthreads();
#pragma unroll
        for (int jj = 0; jj < 64; jj++) {
            float hv = sh[lane][jj];
            acc0 = fmaf(hv, sw[w][jj], acc0);
            acc1 = fmaf(hv, sw[w + 8][jj], acc1);
        }
        __syncthreads();
    }
    int c0 = cBase + w, c1 = cBase + w + 8;
    if (c0 < CC) out[lane * CC + c0] = acc0 + bf[c0];
    if (c1 < CC) out[lane * CC + c1] = acc1 + bf[c1];
}

extern "C" void kernel_launch(void* const* d_in, const int* in_sizes, int n_in,
                              void* d_out, int out_size) {
    (void)in_sizes; (void)n_in; (void)out_size;
    const int*   x   = (const int*)d_in[0];
    const float* emb = (const float*)d_in[1];
    const float* w1  = (const float*)d_in[2];
    const float* b1  = (const float*)d_in[3];
    const float* w2  = (const float*)d_in[4];
    const float* b2  = (const float*)d_in[5];
    const float* wf  = (const float*)d_in[6];
    const float* bf  = (const float*)d_in[7];
    float* out = (float*)d_out;

    k_gather<<<dim3(32, 32), 256>>>(x, emb);
    k_conv1<<<dim3(128, 32), 256>>>(w1, b1);
    k_conv2<<<dim3(64, 32), 256>>>(w2, b2);
    k_fc<<<63, 256>>>(wf, bf, out);
}

// round 8
// speedup vs baseline: 1.0007x; 1.0003x over previous
#include <cuda_runtime.h>

#define BB   32
#define SS   1024
#define DD   256
#define L1   1030      // conv1 output length
#define L1P  1036      // padded
#define KSEL 515       // k-max k for layer 1
#define CH1  768       // channels after fold1 (128 groups x 6)
#define L2IN 515
#define L2   519       // conv2 output length
#define L2PAD 523
#define CH2  896       // channels after fold2 (64 x 14)
#define CC   1000
#define KF   3584

// scratch (static device globals; no runtime allocation)
__device__ float g_h0[BB * DD * SS];      // (b, d, s) embedded+transposed
__device__ float g_h1[BB * CH1 * KSEL];   // (b, c1, pos) after kmax+tanh
__device__ float g_h3[BB * CH2 * 4];      // (b, c2, 4) after top4+tanh

__device__ __forceinline__ unsigned int f2key(float v) {
    unsigned int u = __float_as_uint(v);
    return u ^ ((u & 0x80000000u) ? 0xFFFFFFFFu : 0x80000000u);
}
__device__ __forceinline__ float key2f(unsigned int k) {
    unsigned int u = k ^ ((k & 0x80000000u) ? 0x80000000u : 0xFFFFFFFFu);
    return __uint_as_float(u);
}

// ---------------------------------------------------------------------------
// Kernel 1: embedding gather + transpose  (B,S) tokens -> g_h0 (b, d, s)
// ---------------------------------------------------------------------------
__global__ __launch_bounds__(256) void k_gather(const int* __restrict__ x,
                                                const float* __restrict__ emb) {
    __shared__ float tile[32][257];
    __shared__ int toks[32];
    int b = blockIdx.y;
    int sBase = blockIdx.x * 32;
    int t = threadIdx.x;
    if (t < 32) toks[t] = x[b * SS + sBase + t];
    __syncthreads();
#pragma unroll 4
    for (int i = 0; i < 32; i++)
        tile[i][t] = emb[(unsigned)toks[i] * DD + t];   // coalesced 1KB row read
    __syncthreads();
    int sl = t & 31, wg = t >> 5;
#pragma unroll 4
    for (int r = 0; r < 32; r++) {
        int d = wg * 32 + r;
        g_h0[((b * DD + d) << 10) + sBase + sl] = tile[sl][d];  // coalesced write
    }
}

// block-wide exclusive scan of packed u64 counters (256 threads)
__device__ __forceinline__ unsigned long long scanExcl64(unsigned long long v,
                                                         unsigned long long* tmp) {
    int lane = threadIdx.x & 31, wid = threadIdx.x >> 5;
    unsigned long long inc = v;
#pragma unroll
    for (int o = 1; o < 32; o <<= 1) {
        unsigned long long n = __shfl_up_sync(0xffffffffu, inc, o);
        if (lane >= o) inc += n;
    }
    if (lane == 31) tmp[wid] = inc;
    __syncthreads();
    unsigned long long off = 0;
#pragma unroll
    for (int w = 0; w < 8; w++)
        if (w < wid) off += tmp[w];
    __syncthreads();          // protect tmp for the next scan
    return off + inc - v;
}

// ---------------------------------------------------------------------------
// Kernel 2: conv1(K=7, depthwise) + fold(pair-sum) + order-preserving
//           k-max(515 of 1030) + tanh.   One block per (b, fold-row r).
// ---------------------------------------------------------------------------
__global__ __launch_bounds__(256) void k_conv1(const float* __restrict__ w1,
                                               const float* __restrict__ b1) {
    __shared__ float e0[L1P], e1[L1P];
    __shared__ float wsh[84];     // 12 filter rows x 7 taps
    __shared__ float bsh[6];
    __shared__ unsigned long long redA[8], redB[8];
    __shared__ unsigned long long totA, totB;
    __shared__ int eqRun[6], keptRun[6];

    int r = blockIdx.x, b = blockIdx.y;
    int t = threadIdx.x;
    int lane = t & 31, wid = t >> 5;

    const float* src0 = g_h0 + ((b * DD + 2 * r) << 10);
    for (int m = t; m < L1P; m += 256) {
        float v0 = 0.f, v1 = 0.f;
        if (m >= 6 && m < 6 + SS) { v0 = src0[m - 6]; v1 = src0[SS + m - 6]; }
        e0[m] = v0; e1[m] = v1;
    }
    if (t < 84) {
        int fr = t / 7, k = t - fr * 7;
        int o = (fr < 6) ? ((2 * r) * 6 + fr) : ((2 * r + 1) * 6 + (fr - 6));
        wsh[t] = w1[o * 7 + k];
    }
    if (t < 6) {
        bsh[t] = b1[(2 * r) * 6 + t] + b1[(2 * r + 1) * 6 + t];
        eqRun[t] = 0; keptRun[t] = 0;
    }
    __syncthreads();

    // compute conv+fold for 6 rows, keep monotonic keys in registers
    unsigned int key[6][5];
#pragma unroll
    for (int f = 0; f < 6; f++) {
#pragma unroll
        for (int i = 0; i < 5; i++) {
            int l = i * 256 + t;
            unsigned int kk = 0u;
            if (l < L1) {
                float acc = bsh[f];
#pragma unroll
                for (int k = 0; k < 7; k++)
                    acc = fmaf(e0[l + k], wsh[f * 7 + k],
                          fmaf(e1[l + k], wsh[(f + 6) * 7 + k], acc));
                kk = f2key(acc);
            }
            key[f][i] = kk;
        }
    }

    // bitwise binary search for the 515th-largest key of each of the 6 rows
    unsigned int T[6] = {0, 0, 0, 0, 0, 0};
    for (int bit = 31; bit >= 0; bit--) {
        unsigned int bm = 1u << bit;
        unsigned int c0 = 0, c1 = 0, c2 = 0, c3 = 0, c4 = 0, c5 = 0;
#pragma unroll
        for (int i = 0; i < 5; i++) {
            c0 += (key[0][i] >= (T[0] | bm));
            c1 += (key[1][i] >= (T[1] | bm));
            c2 += (key[2][i] >= (T[2] | bm));
            c3 += (key[3][i] >= (T[3] | bm));
            c4 += (key[4][i] >= (T[4] | bm));
            c5 += (key[5][i] >= (T[5] | bm));
        }
        unsigned long long pa = (unsigned long long)c0 |
                                ((unsigned long long)c1 << 21) |
                                ((unsigned long long)c2 << 42);
        unsigned long long pb = (unsigned long long)c3 |
                                ((unsigned long long)c4 << 21) |
                                ((unsigned long long)c5 << 42);
#pragma unroll
        for (int o = 16; o; o >>= 1) {
            pa += __shfl_down_sync(0xffffffffu, pa, o);
            pb += __shfl_down_sync(0xffffffffu, pb, o);
        }
        if (lane == 0) { redA[wid] = pa; redB[wid] = pb; }
        __syncthreads();
        if (t == 0) {
            unsigned long long sa = 0, sb = 0;
#pragma unroll
            for (int w = 0; w < 8; w++) { sa += redA[w]; sb += redB[w]; }
            totA = sa; totB = sb;
        }
        __syncthreads();
        unsigned long long sa = totA, sb = totB;
        if (((sa)       & 0x1FFFFFu) >= KSEL) T[0] |= bm;
        if (((sa >> 21) & 0x1FFFFFu) >= KSEL) T[1] |= bm;
        if (((sa >> 42) & 0x1FFFFFu) >= KSEL) T[2] |= bm;
        if (((sb)       & 0x1FFFFFu) >= KSEL) T[3] |= bm;
        if (((sb >> 21) & 0x1FFFFFu) >= KSEL) T[4] |= bm;
        if (((sb >> 42) & 0x1FFFFFu) >= KSEL) T[5] |= bm;
    }

    // g = count(key > T); limit = KSEL - g equal-to-threshold elements kept
    int limit[6];
    {
        unsigned int c0 = 0, c1 = 0, c2 = 0, c3 = 0, c4 = 0, c5 = 0;
#pragma unroll
        for (int i = 0; i < 5; i++) {
            c0 += (key[0][i] > T[0]);
            c1 += (key[1][i] > T[1]);
            c2 += (key[2][i] > T[2]);
            c3 += (key[3][i] > T[3]);
            c4 += (key[4][i] > T[4]);
            c5 += (key[5][i] > T[5]);
        }
        unsigned long long pa = (unsigned long long)c0 |
                                ((unsigned long long)c1 << 21) |
                                ((unsigned long long)c2 << 42);
        unsigned long long pb = (unsigned long long)c3 |
                                ((unsigned long long)c4 << 21) |
                                ((unsigned long long)c5 << 42);
#pragma unroll
        for (int o = 16; o; o >>= 1) {
            pa += __shfl_down_sync(0xffffffffu, pa, o);
            pb += __shfl_down_sync(0xffffffffu, pb, o);
        }
        if (lane == 0) { redA[wid] = pa; redB[wid] = pb; }
        __syncthreads();
        if (t == 0) {
            unsigned long long sa = 0, sb = 0;
#pragma unroll
            for (int w = 0; w < 8; w++) { sa += redA[w]; sb += redB[w]; }
            totA = sa; totB = sb;
        }
        __syncthreads();
        unsigned long long sa = totA, sb = totB;
        limit[0] = KSEL - (int)((sa)       & 0x1FFFFFu);
        limit[1] = KSEL - (int)((sa >> 21) & 0x1FFFFFu);
        limit[2] = KSEL - (int)((sa >> 42) & 0x1FFFFFu);
        limit[3] = KSEL - (int)((sb)       & 0x1FFFFFu);
        limit[4] = KSEL - (int)((sb >> 21) & 0x1FFFFFu);
        limit[5] = KSEL - (int)((sb >> 42) & 0x1FFFFFu);
    }

    // stable (order-preserving) compaction with tanh on write
    float* outBase = g_h1 + (unsigned)(b * CH1 + r * 6) * KSEL;
#pragma unroll
    for (int i = 0; i < 5; i++) {
        int l = i * 256 + t;
        int valid = (l < L1);
        unsigned int isG[6], isE[6];
        unsigned long long ep = 0;
#pragma unroll
        for (int f = 0; f < 6; f++) {
            unsigned int kk = key[f][i];
            isG[f] = valid && (kk > T[f]);
            isE[f] = valid && (kk == T[f]);
            ep |= (unsigned long long)isE[f] << (9 * f);
        }
        unsigned long long eEx = scanExcl64(ep, redA);
        unsigned long long kp = 0;
        unsigned int kept[6];
#pragma unroll
        for (int f = 0; f < 6; f++) {
            int eqB = eqRun[f] + (int)((eEx >> (9 * f)) & 511u);
            kept[f] = isG[f] | (isE[f] & (unsigned)(eqB < limit[f]));
            kp |= (unsigned long long)kept[f] << (9 * f);
        }
        unsigned long long kEx = scanExcl64(kp, redA);
#pragma unroll
        for (int f = 0; f < 6; f++) {
            if (kept[f]) {
                int pos = keptRun[f] + (int)((kEx >> (9 * f)) & 511u);
                outBase[f * KSEL + pos] = tanhf(key2f(key[f][i]));
            }
        }
        __syncthreads();
        if (t == 255) {
            unsigned long long eInc = eEx + ep, kInc = kEx + kp;
#pragma unroll
            for (int f = 0; f < 6; f++) {
                eqRun[f]   += (int)((eInc >> (9 * f)) & 511u);
                keptRun[f] += (int)((kInc >> (9 * f)) & 511u);
            }
        }
        __syncthreads();
    }
}

// top-4 merge of two descending sorted-4 u64 lists (bitonic halver + cleanup)
#define MERGE4(a0, a1, a2, a3, q0, q1, q2, q3)                                  \
    {                                                                           \
        unsigned long long m0 = (a0) > (q3) ? (a0) : (q3);                      \
        unsigned long long m1 = (a1) > (q2) ? (a1) : (q2);                      \
        unsigned long long m2 = (a2) > (q1) ? (a2) : (q1);                      \
        unsigned long long m3 = (a3) > (q0) ? (a3) : (q0);                      \
        unsigned long long d0 = m0 > m2 ? m0 : m2, d2 = m0 > m2 ? m2 : m0;      \
        unsigned long long d1 = m1 > m3 ? m1 : m3, d3 = m1 > m3 ? m3 : m1;      \
        a0 = d0 > d1 ? d0 : d1; a1 = d0 > d1 ? d1 : d0;                         \
        a2 = d2 > d3 ? d2 : d3; a3 = d2 > d3 ? d3 : d2;                         \
    }

// ---------------------------------------------------------------------------
// Kernel 3: conv2(K=5, grouped 6->14) + fold + order-preserving top-4 + tanh
//           One block per (b, fold-row r2). Never materializes conv2 output.
// ---------------------------------------------------------------------------
__global__ __launch_bounds__(256) void k_conv2(const float* __restrict__ w2,
                                               const float* __restrict__ b2) {
    __shared__ float in[12][L2PAD];
    __shared__ float wsh[840];   // 28 filter rows x 30 (6 ich x 5 taps)
    __shared__ float bsh[14];
    __shared__ unsigned long long lists[8][4];

    int r2 = blockIdx.x, b = blockIdx.y;
    int t = threadIdx.x, lane = t & 31, wid = t >> 5;

    const float* src = g_h1 + (unsigned)(b * CH1 + r2 * 12) * KSEL;
    for (int idx = t; idx < 12 * L2PAD; idx += 256) {
        int row = idx / L2PAD, m = idx - row * L2PAD;
        float v = 0.f;
        if (m >= 4 && m < 4 + L2IN) v = src[row * KSEL + (m - 4)];
        in[row][m] = v;
    }
    for (int idx = t; idx < 840; idx += 256) {
        int fr = idx / 30, rem = idx - fr * 30;
        int g = 2 * r2 + (fr >= 14);
        int f = (fr >= 14) ? fr - 14 : fr;
        wsh[idx] = w2[(g * 14 + f) * 30 + rem];
    }
    if (t < 14) bsh[t] = b2[(2 * r2) * 14 + t] + b2[(2 * r2 + 1) * 14 + t];
    __syncthreads();

    for (int f = 0; f < 14; f++) {
        unsigned long long s0 = 0, s1 = 0, s2 = 0, s3 = 0;
        const float* wa = wsh + f * 30;
        const float* wb = wsh + (14 + f) * 30;
#pragma unroll
        for (int i = 0; i < 3; i++) {
            int l = i * 256 + t;
            if (l < L2) {
                float acc = bsh[f];
#pragma unroll
                for (int ci = 0; ci < 6; ci++) {
#pragma unroll
                    for (int k = 0; k < 5; k++) {
                        acc = fmaf(in[ci][l + k],     wa[ci * 5 + k], acc);
                        acc = fmaf(in[6 + ci][l + k], wb[ci * 5 + k], acc);
                    }
                }
                unsigned long long e = ((unsigned long long)f2key(acc) << 32) |
                                       (unsigned int)(1023 - l);  // lower idx wins ties
                if      (e > s0) { s3 = s2; s2 = s1; s1 = s0; s0 = e; }
                else if (e > s1) { s3 = s2; s2 = s1; s1 = e; }
                else if (e > s2) { s3 = s2; s2 = e; }
                else if (e > s3) { s3 = e; }
            }
        }
        // warp-level merge of sorted-4 lists
#pragma unroll
        for (int off = 16; off; off >>= 1) {
            unsigned long long q0 = __shfl_down_sync(0xffffffffu, s0, off);
            unsigned long long q1 = __shfl_down_sync(0xffffffffu, s1, off);
            unsigned long long q2 = __shfl_down_sync(0xffffffffu, s2, off);
            unsigned long long q3 = __shfl_down_sync(0xffffffffu, s3, off);
            MERGE4(s0, s1, s2, s3, q0, q1, q2, q3)
        }
        if (lane == 0) {
            lists[wid][0] = s0; lists[wid][1] = s1;
            lists[wid][2] = s2; lists[wid][3] = s3;
        }
        __syncthreads();
        if (t == 0) {
            unsigned long long a0 = lists[0][0], a1 = lists[0][1];
            unsigned long long a2 = lists[0][2], a3 = lists[0][3];
            for (int w = 1; w < 8; w++) {
                unsigned long long q0 = lists[w][0], q1 = lists[w][1];
                unsigned long long q2 = lists[w][2], q3 = lists[w][3];
                MERGE4(a0, a1, a2, a3, q0, q1, q2, q3)
            }
            unsigned long long ss[4] = {a0, a1, a2, a3};
            int   idx4[4]; float val4[4];
#pragma unroll
            for (int j = 0; j < 4; j++) {
                idx4[j] = 1023 - (int)(unsigned int)(ss[j] & 0xffffffffu);
                val4[j] = key2f((unsigned int)(ss[j] >> 32));
            }
            // restore original index order
#define CSW(a, bq)                                                              \
    if (idx4[a] > idx4[bq]) {                                                   \
        int ti = idx4[a]; idx4[a] = idx4[bq]; idx4[bq] = ti;                    \
        float tv = val4[a]; val4[a] = val4[bq]; val4[bq] = tv;                   \
    }
            CSW(0, 1) CSW(2, 3) CSW(0, 2) CSW(1, 3) CSW(1, 2)
#undef CSW
            float* o = g_h3 + (unsigned)(b * CH2 + (r2 * 14 + f)) * 4;
            o[0] = tanhf(val4[0]); o[1] = tanhf(val4[1]);
            o[2] = tanhf(val4[2]); o[3] = tanhf(val4[3]);
        }
        __syncthreads();
    }
}

// ---------------------------------------------------------------------------
// Kernel 4: out(32,1000) = h3(32,3584) @ wf(1000,3584)^T + bf
// ---------------------------------------------------------------------------
__global__ __launch_bounds__(256) void k_fc(const float* __restrict__ wf,
                                            const float* __restrict__ bf,
                                            float* __restrict__ out) {
    __shared__ float sh[32][65];
    __shared__ float sw[16][64];
    int t = threadIdx.x;
    int cBase = blockIdx.x * 16;
    int lane = t & 31;       // b
    int w = t >> 5;          // 0..7 -> c rows w and w+8
    float acc0 = 0.f, acc1 = 0.f;
    const float* hsrc = g_h3;   // flat (b, 3584)
    for (int kt = 0; kt < 56; kt++) {
        int k0 = kt * 64;
#pragma unroll
        for (int i = 0; i < 8; i++) {
            int idx = t + i * 256;
            int bb = idx >> 6, jj = idx & 63;
            sh[bb][jj] = hsrc[bb * KF + k0 + jj];
        }
#pragma unroll
        for (int i = 0; i < 4; i++) {
            int idx = t + i * 256;
            int rr = idx >> 6, jj = idx & 63;
            int c = cBase + rr;
            sw[rr][jj] = (c < CC) ? wf[c * KF + k0 + jj] : 0.f;
        }
        __syncthreads();
#pragma unroll
        for (int jj = 0; jj < 64; jj++) {
            float hv = sh[lane][jj];
            acc0 = fmaf(hv, sw[w][jj], acc0);
            acc1 = fmaf(hv, sw[w + 8][jj], acc1);
        }
        __syncthreads();
    }
    int c0 = cBase + w, c1 = cBase + w + 8;
    if (c0 < CC) out[lane * CC + c0] = acc0 + bf[c0];
    if (c1 < CC) out[lane * CC + c1] = acc1 + bf[c1];
}

extern "C" void kernel_launch(void* const* d_in, const int* in_sizes, int n_in,
                              void* d_out, int out_size) {
    (void)in_sizes; (void)n_in; (void)out_size;
    const int*   x   = (const int*)d_in[0];
    const float* emb = (const float*)d_in[1];
    const float* w1  = (const float*)d_in[2];
    const float* b1  = (const float*)d_in[3];
    const float* w2  = (const float*)d_in[4];
    const float* b2  = (const float*)d_in[5];
    const float* wf  = (const float*)d_in[6];
    const float* bf  = (const float*)d_in[7];
    float* out = (float*)d_out;

    k_gather<<<dim3(32, 32), 256>>>(x, emb);
    k_conv1<<<dim3(128, 32), 256>>>(w1, b1);
    k_conv2<<<dim3(64, 32), 256>>>(w2, b2);
    k_fc<<<63, 256>>>(wf, bf, out);
}

// round 9
// speedup vs baseline: 1.0013x; 1.0006x over previous
#include <cuda_runtime.h>

#define BB   32
#define SS   1024
#define DD   256
#define L1   1030      // conv1 output length
#define L1P  1036      // padded
#define KSEL 515       // k-max k for layer 1
#define CH1  768       // channels after fold1 (128 groups x 6)
#define L2IN 515
#define L2   519       // conv2 output length
#define L2PAD 523
#define CH2  896       // channels after fold2 (64 x 14)
#define CC   1000
#define KF   3584

// scratch (static device globals; no runtime allocation)
__device__ float g_h0[BB * DD * SS];      // (b, d, s) embedded+transposed
__device__ float g_h1[BB * CH1 * KSEL];   // (b, c1, pos) after kmax+tanh
__device__ float g_h3[BB * CH2 * 4];      // (b, c2, 4) after top4+tanh

__device__ __forceinline__ unsigned int f2key(float v) {
    unsigned int u = __float_as_uint(v);
    return u ^ ((u & 0x80000000u) ? 0xFFFFFFFFu : 0x80000000u);
}
__device__ __forceinline__ float key2f(unsigned int k) {
    unsigned int u = k ^ ((k & 0x80000000u) ? 0x80000000u : 0xFFFFFFFFu);
    return __uint_as_float(u);
}

// ---------------------------------------------------------------------------
// Kernel 1: embedding gather + transpose  (B,S) tokens -> g_h0 (b, d, s)
// ---------------------------------------------------------------------------
__global__ __launch_bounds__(256) void k_gather(const int* __restrict__ x,
                                                const float* __restrict__ emb) {
    __shared__ float tile[32][257];
    __shared__ int toks[32];
    int b = blockIdx.y;
    int sBase = blockIdx.x * 32;
    int t = threadIdx.x;
    if (t < 32) toks[t] = x[b * SS + sBase + t];
    __syncthreads();
#pragma unroll 4
    for (int i = 0; i < 32; i++)
        tile[i][t] = emb[(unsigned)toks[i] * DD + t];   // coalesced 1KB row read
    __syncthreads();
    int sl = t & 31, wg = t >> 5;
#pragma unroll 4
    for (int r = 0; r < 32; r++) {
        int d = wg * 32 + r;
        g_h0[((b * DD + d) << 10) + sBase + sl] = tile[sl][d];  // coalesced write
    }
}

// block-wide exclusive scan of packed u64 counters (256 threads)
__device__ __forceinline__ unsigned long long scanExcl64(unsigned long long v,
                                                         unsigned long long* tmp) {
    int lane = threadIdx.x & 31, wid = threadIdx.x >> 5;
    unsigned long long inc = v;
#pragma unroll
    for (int o = 1; o < 32; o <<= 1) {
        unsigned long long n = __shfl_up_sync(0xffffffffu, inc, o);
        if (lane >= o) inc += n;
    }
    if (lane == 31) tmp[wid] = inc;
    __syncthreads();
    unsigned long long off = 0;
#pragma unroll
    for (int w = 0; w < 8; w++)
        if (w < wid) off += tmp[w];
    __syncthreads();          // protect tmp for the next scan
    return off + inc - v;
}

// ---------------------------------------------------------------------------
// Kernel 2: conv1(K=7, depthwise) + fold(pair-sum) + order-preserving
//           k-max(515 of 1030) + tanh.   One block per (b, fold-row r).
// ---------------------------------------------------------------------------
__global__ __launch_bounds__(256) void k_conv1(const float* __restrict__ w1,
                                               const float* __restrict__ b1) {
    __shared__ float e0[L1P], e1[L1P];
    __shared__ float wsh[84];     // 12 filter rows x 7 taps
    __shared__ float bsh[6];
    __shared__ unsigned long long redA[8], redB[8];
    __shared__ unsigned long long totA, totB;
    __shared__ int eqRun[6], keptRun[6];

    int r = blockIdx.x, b = blockIdx.y;
    int t = threadIdx.x;
    int lane = t & 31, wid = t >> 5;

    const float* src0 = g_h0 + ((b * DD + 2 * r) << 10);
    for (int m = t; m < L1P; m += 256) {
        float v0 = 0.f, v1 = 0.f;
        if (m >= 6 && m < 6 + SS) { v0 = src0[m - 6]; v1 = src0[SS + m - 6]; }
        e0[m] = v0; e1[m] = v1;
    }
    if (t < 84) {
        int fr = t / 7, k = t - fr * 7;
        int o = (fr < 6) ? ((2 * r) * 6 + fr) : ((2 * r + 1) * 6 + (fr - 6));
        wsh[t] = w1[o * 7 + k];
    }
    if (t < 6) {
        bsh[t] = b1[(2 * r) * 6 + t] + b1[(2 * r + 1) * 6 + t];
        eqRun[t] = 0; keptRun[t] = 0;
    }
    __syncthreads();

    // compute conv+fold for 6 rows, keep monotonic keys in registers
    unsigned int key[6][5];
#pragma unroll
    for (int f = 0; f < 6; f++) {
#pragma unroll
        for (int i = 0; i < 5; i++) {
            int l = i * 256 + t;
            unsigned int kk = 0u;
            if (l < L1) {
                float acc = bsh[f];
#pragma unroll
                for (int k = 0; k < 7; k++)
                    acc = fmaf(e0[l + k], wsh[f * 7 + k],
                          fmaf(e1[l + k], wsh[(f + 6) * 7 + k], acc));
                kk = f2key(acc);
            }
            key[f][i] = kk;
        }
    }

    // bitwise binary search for the 515th-largest key of each of the 6 rows
    unsigned int T[6] = {0, 0, 0, 0, 0, 0};
    for (int bit = 31; bit >= 0; bit--) {
        unsigned int bm = 1u << bit;
        unsigned int c0 = 0, c1 = 0, c2 = 0, c3 = 0, c4 = 0, c5 = 0;
#pragma unroll
        for (int i = 0; i < 5; i++) {
            c0 += (key[0][i] >= (T[0] | bm));
            c1 += (key[1][i] >= (T[1] | bm));
            c2 += (key[2][i] >= (T[2] | bm));
            c3 += (key[3][i] >= (T[3] | bm));
            c4 += (key[4][i] >= (T[4] | bm));
            c5 += (key[5][i] >= (T[5] | bm));
        }
        unsigned long long pa = (unsigned long long)c0 |
                                ((unsigned long long)c1 << 21) |
                                ((unsigned long long)c2 << 42);
        unsigned long long pb = (unsigned long long)c3 |
                                ((unsigned long long)c4 << 21) |
                                ((unsigned long long)c5 << 42);
#pragma unroll
        for (int o = 16; o; o >>= 1) {
            pa += __shfl_down_sync(0xffffffffu, pa, o);
            pb += __shfl_down_sync(0xffffffffu, pb, o);
        }
        if (lane == 0) { redA[wid] = pa; redB[wid] = pb; }
        __syncthreads();
        if (t == 0) {
            unsigned long long sa = 0, sb = 0;
#pragma unroll
            for (int w = 0; w < 8; w++) { sa += redA[w]; sb += redB[w]; }
            totA = sa; totB = sb;
        }
        __syncthreads();
        unsigned long long sa = totA, sb = totB;
        if (((sa)       & 0x1FFFFFu) >= KSEL) T[0] |= bm;
        if (((sa >> 21) & 0x1FFFFFu) >= KSEL) T[1] |= bm;
        if (((sa >> 42) & 0x1FFFFFu) >= KSEL) T[2] |= bm;
        if (((sb)       & 0x1FFFFFu) >= KSEL) T[3] |= bm;
        if (((sb >> 21) & 0x1FFFFFu) >= KSEL) T[4] |= bm;
        if (((sb >> 42) & 0x1FFFFFu) >= KSEL) T[5] |= bm;
    }

    // g = count(key > T); limit = KSEL - g equal-to-threshold elements kept
    int limit[6];
    {
        unsigned int c0 = 0, c1 = 0, c2 = 0, c3 = 0, c4 = 0, c5 = 0;
#pragma unroll
        for (int i = 0; i < 5; i++) {
            c0 += (key[0][i] > T[0]);
            c1 += (key[1][i] > T[1]);
            c2 += (key[2][i] > T[2]);
            c3 += (key[3][i] > T[3]);
            c4 += (key[4][i] > T[4]);
            c5 += (key[5][i] > T[5]);
        }
        unsigned long long pa = (unsigned long long)c0 |
                                ((unsigned long long)c1 << 21) |
                                ((unsigned long long)c2 << 42);
        unsigned long long pb = (unsigned long long)c3 |
                                ((unsigned long long)c4 << 21) |
                                ((unsigned long long)c5 << 42);
#pragma unroll
        for (int o = 16; o; o >>= 1) {
            pa += __shfl_down_sync(0xffffffffu, pa, o);
            pb += __shfl_down_sync(0xffffffffu, pb, o);
        }
        if (lane == 0) { redA[wid] = pa; redB[wid] = pb; }
        __syncthreads();
        if (t == 0) {
            unsigned long long sa = 0, sb = 0;
#pragma unroll
            for (int w = 0; w < 8; w++) { sa += redA[w]; sb += redB[w]; }
            totA = sa; totB = sb;
        }
        __syncthreads();
        unsigned long long sa = totA, sb = totB;
        limit[0] = KSEL - (int)((sa)       & 0x1FFFFFu);
        limit[1] = KSEL - (int)((sa >> 21) & 0x1FFFFFu);
        limit[2] = KSEL - (int)((sa >> 42) & 0x1FFFFFu);
        limit[3] = KSEL - (int)((sb)       & 0x1FFFFFu);
        limit[4] = KSEL - (int)((sb >> 21) & 0x1FFFFFu);
        limit[5] = KSEL - (int)((sb >> 42) & 0x1FFFFFu);
    }

    // stable (order-preserving) compaction with tanh on write
    float* outBase = g_h1 + (unsigned)(b * CH1 + r * 6) * KSEL;
#pragma unroll
    for (int i = 0; i < 5; i++) {
        int l = i * 256 + t;
        int valid = (l < L1);
        unsigned int isG[6], isE[6];
        unsigned long long ep = 0;
#pragma unroll
        for (int f = 0; f < 6; f++) {
            unsigned int kk = key[f][i];
            isG[f] = valid && (kk > T[f]);
            isE[f] = valid && (kk == T[f]);
            ep |= (unsigned long long)isE[f] << (9 * f);
        }
        unsigned long long eEx = scanExcl64(ep, redA);
        unsigned long long kp = 0;
        unsigned int kept[6];
#pragma unroll
        for (int f = 0; f < 6; f++) {
            int eqB = eqRun[f] + (int)((eEx >> (9 * f)) & 511u);
            kept[f] = isG[f] | (isE[f] & (unsigned)(eqB < limit[f]));
            kp |= (unsigned long long)kept[f] << (9 * f);
        }
        unsigned long long kEx = scanExcl64(kp, redA);
#pragma unroll
        for (int f = 0; f < 6; f++) {
            if (kept[f]) {
                int pos = keptRun[f] + (int)((kEx >> (9 * f)) & 511u);
                outBase[f * KSEL + pos] = tanhf(key2f(key[f][i]));
            }
        }
        __syncthreads();
        if (t == 255) {
            unsigned long long eInc = eEx + ep, kInc = kEx + kp;
#pragma unroll
            for (int f = 0; f < 6; f++) {
                eqRun[f]   += (int)((eInc >> (9 * f)) & 511u);
                keptRun[f] += (int)((kInc >> (9 * f)) & 511u);
            }
        }
        __syncthreads();
    }
}

// top-4 merge of two descending sorted-4 u64 lists (bitonic halver + cleanup)
#define MERGE4(a0, a1, a2, a3, q0, q1, q2, q3)                                  \
    {                                                                           \
        unsigned long long m0 = (a0) > (q3) ? (a0) : (q3);                      \
        unsigned long long m1 = (a1) > (q2) ? (a1) : (q2);                      \
        unsigned long long m2 = (a2) > (q1) ? (a2) : (q1);                      \
        unsigned long long m3 = (a3) > (q0) ? (a3) : (q0);                      \
        unsigned long long d0 = m0 > m2 ? m0 : m2, d2 = m0 > m2 ? m2 : m0;      \
        unsigned long long d1 = m1 > m3 ? m1 : m3, d3 = m1 > m3 ? m3 : m1;      \
        a0 = d0 > d1 ? d0 : d1; a1 = d0 > d1 ? d1 : d0;                         \
        a2 = d2 > d3 ? d2 : d3; a3 = d2 > d3 ? d3 : d2;                         \
    }

// ---------------------------------------------------------------------------
// Kernel 3: conv2(K=5, grouped 6->14) + fold + order-preserving top-4 + tanh
//           One block per (b, fold-row r2). Never materializes conv2 output.
// ---------------------------------------------------------------------------
__global__ __launch_bounds__(256) void k_conv2(const float* __restrict__ w2,
                                               const float* __restrict__ b2) {
    __shared__ float in[12][L2PAD];
    __shared__ float wsh[840];   // 28 filter rows x 30 (6 ich x 5 taps)
    __shared__ float bsh[14];
    __shared__ unsigned long long lists[8][4];

    int r2 = blockIdx.x, b = blockIdx.y;
    int t = threadIdx.x, lane = t & 31, wid = t >> 5;

    const float* src = g_h1 + (unsigned)(b * CH1 + r2 * 12) * KSEL;
    for (int idx = t; idx < 12 * L2PAD; idx += 256) {
        int row = idx / L2PAD, m = idx - row * L2PAD;
        float v = 0.f;
        if (m >= 4 && m < 4 + L2IN) v = src[row * KSEL + (m - 4)];
        in[row][m] = v;
    }
    for (int idx = t; idx < 840; idx += 256) {
        int fr = idx / 30, rem = idx - fr * 30;
        int g = 2 * r2 + (fr >= 14);
        int f = (fr >= 14) ? fr - 14 : fr;
        wsh[idx] = w2[(g * 14 + f) * 30 + rem];
    }
    if (t < 14) bsh[t] = b2[(2 * r2) * 14 + t] + b2[(2 * r2 + 1) * 14 + t];
    __syncthreads();

    for (int f = 0; f < 14; f++) {
        unsigned long long s0 = 0, s1 = 0, s2 = 0, s3 = 0;
        const float* wa = wsh + f * 30;
        const float* wb = wsh + (14 + f) * 30;
#pragma unroll
        for (int i = 0; i < 3; i++) {
            int l = i * 256 + t;
            if (l < L2) {
                float acc = bsh[f];
#pragma unroll
                for (int ci = 0; ci < 6; ci++) {
#pragma unroll
                    for (int k = 0; k < 5; k++) {
                        acc = fmaf(in[ci][l + k],     wa[ci * 5 + k], acc);
                        acc = fmaf(in[6 + ci][l + k], wb[ci * 5 + k], acc);
                    }
                }
                unsigned long long e = ((unsigned long long)f2key(acc) << 32) |
                                       (unsigned int)(1023 - l);  // lower idx wins ties
                if      (e > s0) { s3 = s2; s2 = s1; s1 = s0; s0 = e; }
                else if (e > s1) { s3 = s2; s2 = s1; s1 = e; }
                else if (e > s2) { s3 = s2; s2 = e; }
                else if (e > s3) { s3 = e; }
            }
        }
        // warp-level merge of sorted-4 lists
#pragma unroll
        for (int off = 16; off; off >>= 1) {
            unsigned long long q0 = __shfl_down_sync(0xffffffffu, s0, off);
            unsigned long long q1 = __shfl_down_sync(0xffffffffu, s1, off);
            unsigned long long q2 = __shfl_down_sync(0xffffffffu, s2, off);
            unsigned long long q3 = __shfl_down_sync(0xffffffffu, s3, off);
            MERGE4(s0, s1, s2, s3, q0, q1, q2, q3)
        }
        if (lane == 0) {
            lists[wid][0] = s0; lists[wid][1] = s1;
            lists[wid][2] = s2; lists[wid][3] = s3;
        }
        __syncthreads();
        if (t == 0) {
            unsigned long long a0 = lists[0][0], a1 = lists[0][1];
            unsigned long long a2 = lists[0][2], a3 = lists[0][3];
            for (int w = 1; w < 8; w++) {
                unsigned long long q0 = lists[w][0], q1 = lists[w][1];
                unsigned long long q2 = lists[w][2], q3 = lists[w][3];
                MERGE4(a0, a1, a2, a3, q0, q1, q2, q3)
            }
            unsigned long long ss[4] = {a0, a1, a2, a3};
            int   idx4[4]; float val4[4];
#pragma unroll
            for (int j = 0; j < 4; j++) {
                idx4[j] = 1023 - (int)(unsigned int)(ss[j] & 0xffffffffu);
                val4[j] = key2f((unsigned int)(ss[j] >> 32));
            }
            // restore original index order
#define CSW(a, bq)                                                              \
    if (idx4[a] > idx4[bq]) {                                                   \
        int ti = idx4[a]; idx4[a] = idx4[bq]; idx4[bq] = ti;                    \
        float tv = val4[a]; val4[a] = val4[bq]; val4[bq] = tv;                   \
    }
            CSW(0, 1) CSW(2, 3) CSW(0, 2) CSW(1, 3) CSW(1, 2)
#undef CSW
            float* o = g_h3 + (unsigned)(b * CH2 + (r2 * 14 + f)) * 4;
            o[0] = tanhf(val4[0]); o[1] = tanhf(val4[1]);
            o[2] = tanhf(val4[2]); o[3] = tanhf(val4[3]);
        }
        __syncthreads();
    }
}

// ---------------------------------------------------------------------------
// Kernel 4: out(32,1000) = h3(32,3584) @ wf(1000,3584)^T + bf
// ---------------------------------------------------------------------------
__global__ __launch_bounds__(256) void k_fc(const float* __restrict__ wf,
                                            const float* __restrict__ bf,
                                            float* __restrict__ out) {
    __shared__ float sh[32][65];
    __shared__ float sw[16][64];
    int t = threadIdx.x;
    int cBase = blockIdx.x * 16;
    int lane = t & 31;       // b
    int w = t >> 5;          // 0..7 -> c rows w and w+8
    float acc0 = 0.f, acc1 = 0.f;
    const float* hsrc = g_h3;   // flat (b, 3584)
    for (int kt = 0; kt < 56; kt++) {
        int k0 = kt * 64;
#pragma unroll
        for (int i = 0; i < 8; i++) {
            int idx = t + i * 256;
            int bb = idx >> 6, jj = idx & 63;
            sh[bb][jj] = hsrc[bb * KF + k0 + jj];
        }
#pragma unroll
        for (int i = 0; i < 4; i++) {
            int idx = t + i * 256;
            int rr = idx >> 6, jj = idx & 63;
            int c = cBase + rr;
            sw[rr][jj] = (c < CC) ? wf[c * KF + k0 + jj] : 0.f;
        }
        __syncthreads();
#pragma unroll
        for (int jj = 0; jj < 64; jj++) {
            float hv = sh[lane][jj];
            acc0 = fmaf(hv, sw[w][jj], acc0);
            acc1 = fmaf(hv, sw[w + 8][jj], acc1);
        }
        __syncthreads();
    }
    int c0 = cBase + w, c1 = cBase + w + 8;
    if (c0 < CC) out[lane * CC + c0] = acc0 + bf[c0];
    if (c1 < CC) out[lane * CC + c1] = acc1 + bf[c1];
}

extern "C" void kernel_launch(void* const* d_in, const int* in_sizes, int n_in,
                              void* d_out, int out_size) {
    (void)in_sizes; (void)n_in; (void)out_size;
    const int*   x   = (const int*)d_in[0];
    const float* emb = (const float*)d_in[1];
    const float* w1  = (const float*)d_in[2];
    const float* b1  = (const float*)d_in[3];
    const float* w2  = (const float*)d_in[4];
    const float* b2  = (const float*)d_in[5];
    const float* wf  = (const float*)d_in[6];
    const float* bf  = (const float*)d_in[7];
    float* out = (float*)d_out;

    k_gather<<<dim3(32, 32), 256>>>(x, emb);
    k_conv1<<<dim3(128, 32), 256>>>(w1, b1);
    k_conv2<<<dim3(64, 32), 256>>>(w2, b2);
    k_fc<<<63, 256>>>(wf, bf, out);
}

// round 10
// speedup vs baseline: 1.8199x; 1.8176x over previous
#include <cuda_runtime.h>

#define BB   32
#define SS   1024
#define DD   256
#define L1   1030      // conv1 output length
#define KSEL 515       // k-max k for layer 1
#define CH1  768       // channels after fold1 (128 groups x 6)
#define L2IN 515
#define L2   519       // conv2 output length
#define CH2  896       // channels after fold2 (64 x 14)
#define CC   1000
#define KF   3584
#define KSPLIT 8

// scratch (static device globals; no runtime allocation)
__device__ float g_h0[BB * DD * SS];      // (b, d, s) embedded+transposed
__device__ float g_h1[BB * CH1 * KSEL];   // (b, c1, pos) after kmax+tanh
__device__ float g_h3[BB * CH2 * 4];      // (b, c2, 4) after top4+tanh
__device__ float g_fcp[KSPLIT * BB * CC]; // fc partial sums

__device__ __forceinline__ unsigned int f2key(float v) {
    unsigned int u = __float_as_uint(v);
    return u ^ ((u & 0x80000000u) ? 0xFFFFFFFFu : 0x80000000u);
}
__device__ __forceinline__ float key2f(unsigned int k) {
    unsigned int u = k ^ ((k & 0x80000000u) ? 0x80000000u : 0xFFFFFFFFu);
    return __uint_as_float(u);
}
__device__ __forceinline__ float fast_tanh(float x) {
    float ax = fabsf(x);
    float t = __expf(-2.f * ax);
    float r = __fdividef(1.f - t, 1.f + t);
    return copysignf(r, x);
}

// packed f32x2 helpers (sm_103a FFMA2 path)
__device__ __forceinline__ unsigned long long pk2(float lo, float hi) {
    unsigned long long r;
    asm("mov.b64 %0, {%1,%2};" : "=l"(r) : "f"(lo), "f"(hi));
    return r;
}
__device__ __forceinline__ void upk2(unsigned long long v, float& lo, float& hi) {
    asm("mov.b64 {%0,%1}, %2;" : "=f"(lo), "=f"(hi) : "l"(v));
}
__device__ __forceinline__ void fma2(unsigned long long& d, unsigned long long a,
                                     unsigned long long b) {
    asm("fma.rn.f32x2 %0, %1, %2, %3;" : "=l"(d) : "l"(a), "l"(b), "l"(d));
}

// warp exclusive scan (int)
__device__ __forceinline__ int wexscan(int v, int lane) {
    int s = v;
#pragma unroll
    for (int o = 1; o < 32; o <<= 1) {
        int n = __shfl_up_sync(0xffffffffu, s, o);
        if (lane >= o) s += n;
    }
    return s - v;
}

// ---------------------------------------------------------------------------
// Kernel 1: embedding gather + transpose  (B,S) tokens -> g_h0 (b, d, s)
// ---------------------------------------------------------------------------
__global__ __launch_bounds__(256) void k_gather(const int* __restrict__ x,
                                                const float* __restrict__ emb) {
    __shared__ float tile[32][257];
    __shared__ int toks[32];
    int b = blockIdx.y;
    int sBase = blockIdx.x * 32;
    int t = threadIdx.x;
    if (t < 32) toks[t] = x[b * SS + sBase + t];
    __syncthreads();
#pragma unroll 4
    for (int i = 0; i < 32; i++)
        tile[i][t] = emb[(unsigned)toks[i] * DD + t];
    __syncthreads();
    int sl = t & 31, wg = t >> 5;
#pragma unroll 4
    for (int r = 0; r < 32; r++) {
        int d = wg * 32 + r;
        g_h0[((b * DD + d) << 10) + sBase + sl] = tile[sl][d];
    }
}

// ---------------------------------------------------------------------------
// Kernel 2: conv1(K=7, depthwise, packed FMA2) + fold + order-preserving
//           k-max(515 of 1030) + tanh.  One WARP per selection row.
//           Block = 192 threads = 6 warps = 6 filters of one fold-row.
// ---------------------------------------------------------------------------
__global__ __launch_bounds__(192) void k_conv1(const float* __restrict__ w1,
                                               const float* __restrict__ b1) {
    __shared__ float e0[1064], e1[1064];
    __shared__ unsigned int act[6][L1];   // per-warp active buffer

    int r = blockIdx.x;        // fold row 0..127
    int b = blockIdx.y;
    int t = threadIdx.x;
    int w = t >> 5, lane = t & 31;

    // stage the two input channels (zero-padded both sides)
    const float* s0 = g_h0 + ((b * DD + 2 * r) << 10);
    for (int m = t; m < 1064; m += 192) {
        float v0 = 0.f, v1 = 0.f;
        if (m >= 6 && m < 6 + SS) { v0 = s0[m - 6]; v1 = s0[SS + m - 6]; }
        e0[m] = v0; e1[m] = v1;
    }
    __syncthreads();

    int f = w;                            // filter 0..5
    int o0 = (2 * r) * 6 + f, o1 = (2 * r + 1) * 6 + f;
    float bias = b1[o0] + b1[o1];
    unsigned long long W[7];
#pragma unroll
    for (int k = 0; k < 7; k++) W[k] = pk2(w1[o0 * 7 + k], w1[o1 * 7 + k]);

    int base = lane * 33;                 // lane-contiguous chunk (stable order)
    unsigned int key[33];
    unsigned long long P[7];
#pragma unroll
    for (int k = 0; k < 7; k++) P[k] = pk2(e0[base + k], e1[base + k]);

#pragma unroll
    for (int j = 0; j < 33; j++) {
        unsigned long long acc = pk2(bias, 0.f);
#pragma unroll
        for (int k = 0; k < 7; k++) fma2(acc, P[k], W[k]);
        float lo, hi; upk2(acc, lo, hi);
        float x = lo + hi;
        int pos = base + j;
        unsigned int kk = 0u;
        if (pos < L1) { kk = f2key(x); act[f][pos] = kk; }
        key[j] = kk;
#pragma unroll
        for (int k = 0; k < 6; k++) P[k] = P[k + 1];
        P[6] = pk2(e0[base + j + 7], e1[base + j + 7]);
    }
    __syncwarp();

    // active-set bitwise threshold search (warp-local, no block barriers)
    unsigned int* ab = act[f];
    unsigned int T = 0;
    int g = 0, A = L1;
#pragma unroll 1
    for (int bit = 31; bit >= 0; bit--) {
        unsigned int bm = 1u << bit;
        int chunks = (A + 31) >> 5;
        int c = 0;
        for (int ch = 0; ch < chunks; ch++) {
            int idx = (ch << 5) + lane;
            unsigned int v = (idx < A) ? ab[idx] : 0u;
            int pr = (idx < A) && (v & bm);
            c += __popc(__ballot_sync(0xffffffffu, pr));
        }
        int setSel = (g + c >= KSEL);
        int Anew = setSel ? c : (A - c);
        if (Anew != A) {
            int nA = 0;
            for (int ch = 0; ch < chunks; ch++) {
                int idx = (ch << 5) + lane;
                unsigned int v = (idx < A) ? ab[idx] : 0u;
                int keep = (idx < A) && (((v & bm) != 0u) == (setSel != 0));
                unsigned int bal = __ballot_sync(0xffffffffu, keep);
                int pos = nA + __popc(bal & ((1u << lane) - 1u));
                if (keep) ab[pos] = v;
                nA += __popc(bal);
            }
        }
        if (setSel) T |= bm; else g += c;
        A = Anew;
        __syncwarp();
    }
    int limit = KSEL - g;                 // equal-to-T elements to keep

    // stable compaction from registers (original position order)
    int cntG = 0, cntE = 0;
#pragma unroll
    for (int j = 0; j < 33; j++) {
        int valid = (base + j) < L1;
        cntG += valid && (key[j] > T);
        cntE += valid && (key[j] == T);
    }
    int eqBefore = wexscan(cntE, lane);
    int eqTake = limit - eqBefore;
    if (eqTake < 0) eqTake = 0;
    if (eqTake > cntE) eqTake = cntE;
    int keepCnt = cntG + eqTake;
    int wrBase = wexscan(keepCnt, lane);

    float* orow = g_h1 + (size_t)(b * CH1 + r * 6 + f) * KSEL;
    int eq = eqBefore, wr = wrBase;
#pragma unroll
    for (int j = 0; j < 33; j++) {
        int valid = (base + j) < L1;
        if (valid) {
            int isG = key[j] > T;
            int isE = key[j] == T;
            int kept = isG || (isE && (eq < limit));
            eq += isE;
            if (kept) { orow[wr] = fast_tanh(key2f(key[j])); wr++; }
        }
    }
}

// top-4 merge of two descending sorted-4 u64 lists
#define MERGE4(a0, a1, a2, a3, q0, q1, q2, q3)                                  \
    {                                                                           \
        unsigned long long m0 = (a0) > (q3) ? (a0) : (q3);                      \
        unsigned long long m1 = (a1) > (q2) ? (a1) : (q2);                      \
        unsigned long long m2 = (a2) > (q1) ? (a2) : (q1);                      \
        unsigned long long m3 = (a3) > (q0) ? (a3) : (q0);                      \
        unsigned long long d0 = m0 > m2 ? m0 : m2, d2 = m0 > m2 ? m2 : m0;      \
        unsigned long long d1 = m1 > m3 ? m1 : m3, d3 = m1 > m3 ? m3 : m1;      \
        a0 = d0 > d1 ? d0 : d1; a1 = d0 > d1 ? d1 : d0;                         \
        a2 = d2 > d3 ? d2 : d3; a3 = d2 > d3 ? d3 : d2;                         \
    }
#define INS4(e)                                                                 \
    {                                                                           \
        if ((e) > s0)      { s3 = s2; s2 = s1; s1 = s0; s0 = (e); }             \
        else if ((e) > s1) { s3 = s2; s2 = s1; s1 = (e); }                      \
        else if ((e) > s2) { s3 = s2; s2 = (e); }                               \
        else if ((e) > s3) { s3 = (e); }                                        \
    }

// ---------------------------------------------------------------------------
// Kernel 3: conv2(K=5, grouped 6->14, packed FMA2 over folded groups) +
//           order-preserving top-4 + tanh. One WARP per filter; no per-filter
//           block barriers. Block = 448 threads = 14 warps = one (b, r2).
// ---------------------------------------------------------------------------
__global__ __launch_bounds__(448) void k_conv2(const float* __restrict__ w2,
                                               const float* __restrict__ b2) {
    __shared__ float in[12][552];
    __shared__ float wsh[840];
    __shared__ float bsh[14];

    int r2 = blockIdx.x, b = blockIdx.y;
    int t = threadIdx.x, lane = t & 31, f = t >> 5;

    const float* src = g_h1 + (size_t)(b * CH1 + r2 * 12) * KSEL;
    for (int idx = t; idx < 12 * 552; idx += 448) {
        int row = idx / 552, m = idx - row * 552;
        float v = 0.f;
        if (m >= 4 && m < 4 + L2IN) v = src[row * KSEL + m - 4];
        in[row][m] = v;
    }
    for (int idx = t; idx < 840; idx += 448) {
        int fr = idx / 30, rem = idx - fr * 30;
        int gg = 2 * r2 + (fr >= 14);
        int ff = (fr >= 14) ? fr - 14 : fr;
        wsh[idx] = w2[(gg * 14 + ff) * 30 + rem];
    }
    if (t < 14) bsh[t] = b2[(2 * r2) * 14 + t] + b2[(2 * r2 + 1) * 14 + t];
    __syncthreads();

    unsigned long long wp[30];
#pragma unroll
    for (int i = 0; i < 30; i++) wp[i] = pk2(wsh[f * 30 + i], wsh[(14 + f) * 30 + i]);
    float bias = bsh[f];

    unsigned long long s0 = 0, s1 = 0, s2 = 0, s3 = 0;
    int base = lane * 18;                  // 18 outputs per lane (lanes 0..28)

    if (lane < 29) {
        unsigned long long acc[6];
#pragma unroll
        for (int i = 0; i < 6; i++) acc[i] = 0ull;

#pragma unroll
        for (int cp = 0; cp < 11; cp++) {
            int q0 = 2 * cp;
#pragma unroll
            for (int ci = 0; ci < 6; ci++) {
                float2 a  = *reinterpret_cast<const float2*>(&in[ci][base + q0]);
                float2 c2 = *reinterpret_cast<const float2*>(&in[6 + ci][base + q0]);
                unsigned long long P0 = pk2(a.x, c2.x);
                unsigned long long P1 = pk2(a.y, c2.y);
#pragma unroll
                for (int k = 0; k < 5; k++) {
                    int p0 = q0 - k, p1 = q0 + 1 - k;
                    if (p0 >= 0 && p0 < 18) fma2(acc[(p0 + 12) % 6], P0, wp[ci * 5 + k]);
                    if (p1 >= 0 && p1 < 18) fma2(acc[(p1 + 12) % 6], P1, wp[ci * 5 + k]);
                }
            }
#pragma unroll
            for (int d = 0; d < 2; d++) {
                int pe = 2 * cp - 4 + d;
                if (pe >= 0 && pe < 18) {
                    float lo, hi; upk2(acc[(pe + 12) % 6], lo, hi);
                    float x = lo + hi + bias;
                    int pos = base + pe;
                    if (pos < L2) {
                        unsigned long long e =
                            ((unsigned long long)f2key(x) << 32) |
                            (unsigned int)(1023 - pos);
                        INS4(e)
                    }
                    acc[(pe + 12) % 6] = 0ull;
                }
            }
        }
    }

    // warp merge (all lanes participate; idle lanes contribute zeros)
#pragma unroll
    for (int off = 16; off; off >>= 1) {
        unsigned long long q0 = __shfl_down_sync(0xffffffffu, s0, off);
        unsigned long long q1 = __shfl_down_sync(0xffffffffu, s1, off);
        unsigned long long q2 = __shfl_down_sync(0xffffffffu, s2, off);
        unsigned long long q3 = __shfl_down_sync(0xffffffffu, s3, off);
        MERGE4(s0, s1, s2, s3, q0, q1, q2, q3)
    }
    if (lane == 0) {
        unsigned long long ss[4] = {s0, s1, s2, s3};
        int idx4[4]; float val4[4];
#pragma unroll
        for (int j = 0; j < 4; j++) {
            idx4[j] = 1023 - (int)(unsigned int)(ss[j] & 0xffffffffu);
            val4[j] = key2f((unsigned int)(ss[j] >> 32));
        }
#define CSW(a, bq)                                                              \
    if (idx4[a] > idx4[bq]) {                                                   \
        int ti = idx4[a]; idx4[a] = idx4[bq]; idx4[bq] = ti;                    \
        float tv = val4[a]; val4[a] = val4[bq]; val4[bq] = tv;                   \
    }
        CSW(0, 1) CSW(2, 3) CSW(0, 2) CSW(1, 3) CSW(1, 2)
#undef CSW
        float* o = g_h3 + (size_t)(b * CH2 + (r2 * 14 + f)) * 4;
        o[0] = fast_tanh(val4[0]); o[1] = fast_tanh(val4[1]);
        o[2] = fast_tanh(val4[2]); o[3] = fast_tanh(val4[3]);
    }
}

// ---------------------------------------------------------------------------
// Kernel 4a: split-K GEMM partials: g_fcp[kz] = h3(32,448k) @ wf^T chunk
//            grid (16 cTiles, 8 kSplits), block 256, thread = 2b x 4c
// ---------------------------------------------------------------------------
__global__ __launch_bounds__(256) void k_fcp(const float* __restrict__ wf) {
    __shared__ float sh[32][65];
    __shared__ float sw[64][65];
    int t = threadIdx.x;
    int cb = blockIdx.x, kz = blockIdx.y;
    int bt = t >> 4;        // 0..15  -> b rows 2bt, 2bt+1
    int ct = t & 15;        // 0..15  -> c cols cb*64 + ct*4 + {0..3}
    int k0base = kz * 448;
    float acc[2][4] = {{0.f, 0.f, 0.f, 0.f}, {0.f, 0.f, 0.f, 0.f}};

    for (int kt = 0; kt < 7; kt++) {
        int k0 = k0base + kt * 64;
#pragma unroll
        for (int i = 0; i < 8; i++) {
            int idx = t + i * 256;
            int bb = idx >> 6, kk = idx & 63;
            sh[bb][kk] = g_h3[bb * KF + k0 + kk];
        }
#pragma unroll
        for (int i = 0; i < 16; i++) {
            int idx = t + i * 256;
            int rr = idx >> 6, kk = idx & 63;
            int c = cb * 64 + rr;
            sw[rr][kk] = (c < CC) ? wf[(size_t)c * KF + k0 + kk] : 0.f;
        }
        __syncthreads();
#pragma unroll
        for (int kk = 0; kk < 64; kk++) {
            float a0 = sh[2 * bt][kk], a1 = sh[2 * bt + 1][kk];
#pragma unroll
            for (int j = 0; j < 4; j++) {
                float wv = sw[ct * 4 + j][kk];
                acc[0][j] = fmaf(a0, wv, acc[0][j]);
                acc[1][j] = fmaf(a1, wv, acc[1][j]);
            }
        }
        __syncthreads();
    }
#pragma unroll
    for (int i = 0; i < 2; i++)
#pragma unroll
        for (int j = 0; j < 4; j++) {
            int c = cb * 64 + ct * 4 + j;
            if (c < CC)
                g_fcp[(kz * BB + 2 * bt + i) * CC + c] = acc[i][j];
        }
}

// Kernel 4b: deterministic reduce + bias
__global__ __launch_bounds__(256) void k_fcred(const float* __restrict__ bf,
                                               float* __restrict__ out) {
    int i = blockIdx.x * 256 + threadIdx.x;
    if (i >= BB * CC) return;
    int c = i % CC;
    float s = bf[c];
#pragma unroll
    for (int z = 0; z < KSPLIT; z++) s += g_fcp[z * (BB * CC) + i];
    out[i] = s;
}

extern "C" void kernel_launch(void* const* d_in, const int* in_sizes, int n_in,
                              void* d_out, int out_size) {
    (void)in_sizes; (void)n_in; (void)out_size;
    const int*   x   = (const int*)d_in[0];
    const float* emb = (const float*)d_in[1];
    const float* w1  = (const float*)d_in[2];
    const float* b1  = (const float*)d_in[3];
    const float* w2  = (const float*)d_in[4];
    const float* b2  = (const float*)d_in[5];
    const float* wf  = (const float*)d_in[6];
    const float* bf  = (const float*)d_in[7];
    float* out = (float*)d_out;

    k_gather<<<dim3(32, 32), 256>>>(x, emb);
    k_conv1<<<dim3(128, 32), 192>>>(w1, b1);
    k_conv2<<<dim3(64, 32), 448>>>(w2, b2);
    k_fcp<<<dim3(16, KSPLIT), 256>>>(wf);
    k_fcred<<<125, 256>>>(bf, out);
}